// round 6
// baseline (speedup 1.0000x reference)
#include <cuda_runtime.h>
#include <cuda_bf16.h>
#include <math.h>
#include <stdint.h>

// Problem constants
#define Bsz 128
#define Tt  512
#define Hh  1024
#define Gg  3072
#define KK  1024
#define BTH ((size_t)Bsz * Tt * Hh)

// Recurrence config
#define NCTA 128
#define NTHR 256
#define CH2  32              // k per chunk in fused layer-0 kernel
#define NCH2 (KK / CH2)      // 32

// Tensor GEMM config
#define GT_THREADS 256
#define GT_CHUNK   64
#define GT_NCH     (KK / GT_CHUNK)
#define TILE_B     (128 * 128)
#define BUF_B      (4 * TILE_B)

typedef unsigned long long ull;

// ---------------- device scratch ----------------
__device__ float g_EGX[(size_t)32000 * Gg];          // embGX [32000,3072]
__device__ float g_GX1[(size_t)Tt * Bsz * Gg];       // GX1 [65536,3072]
__device__ __align__(16) __nv_bfloat16 g_Ah[(size_t)32000 * KK];
__device__ __align__(16) __nv_bfloat16 g_Al[(size_t)32000 * KK];
__device__ __align__(16) __nv_bfloat16 g_Wth[(size_t)Gg * KK];  // Wx0^T hi [n][k]
__device__ __align__(16) __nv_bfloat16 g_Wtl[(size_t)Gg * KK];  // Wx0^T lo
__device__ __align__(16) __nv_bfloat16 g_hbh[2][Bsz * Hh];      // ping-pong h hi
__device__ __align__(16) __nv_bfloat16 g_hbl[2][Bsz * Hh];      // ping-pong h lo
__device__ float g_hfin[2][Bsz * Hh];
__device__ unsigned g_bar_count;
__device__ unsigned g_bar_gen;

// ---------------- helpers ----------------
__device__ __forceinline__ uint32_t smem_u32(const void* p)
{
    uint32_t a;
    asm("{ .reg .u64 t; cvta.to.shared.u64 t, %1; cvt.u32.u64 %0, t; }" : "=r"(a) : "l"(p));
    return a;
}

#define SW128(o) ((o) ^ (((o) >> 3) & 0x70))
__device__ __forceinline__ uint32_t sw64(uint32_t o) { return o ^ ((o >> 3) & 0x30); }

#define CP16(dst, src) \
    asm volatile("cp.async.cg.shared.global [%0], [%1], 16;" :: "r"(dst), "l"(src) : "memory")

#define CP_COMMIT() asm volatile("cp.async.commit_group;" ::: "memory")
#define CP_WAIT1()  asm volatile("cp.async.wait_group 1;" ::: "memory")
#define CP_WAIT0()  asm volatile("cp.async.wait_group 0;" ::: "memory")

#define LDSM4(r0, r1, r2, r3, addr) \
    asm volatile("ldmatrix.sync.aligned.m8n8.x4.shared.b16 {%0,%1,%2,%3}, [%4];" \
                 : "=r"(r0), "=r"(r1), "=r"(r2), "=r"(r3) : "r"(addr))

#define LDSM2(r0, r1, addr) \
    asm volatile("ldmatrix.sync.aligned.m8n8.x2.shared.b16 {%0,%1}, [%2];" \
                 : "=r"(r0), "=r"(r1) : "r"(addr))

#define MMA16816(c, a0, a1, a2, a3, b0, b1) \
    asm volatile("mma.sync.aligned.m16n8k16.row.col.f32.bf16.bf16.f32 " \
                 "{%0,%1,%2,%3}, {%4,%5,%6,%7}, {%8,%9}, {%0,%1,%2,%3};" \
                 : "+f"((c)[0]), "+f"((c)[1]), "+f"((c)[2]), "+f"((c)[3]) \
                 : "r"(a0), "r"(a1), "r"(a2), "r"(a3), "r"(b0), "r"(b1))

// ---------------- init ----------------
__global__ void zero_bar()
{
    g_bar_count = 0;
    g_bar_gen   = 0;
}

// ---------------- grid barrier ----------------
__device__ __forceinline__ void grid_barrier()
{
    __threadfence();
    __syncthreads();
    if (threadIdx.x == 0) {
        unsigned gen = *(volatile unsigned*)&g_bar_gen;
        if (atomicAdd(&g_bar_count, 1) == NCTA - 1) {
            g_bar_count = 0;
            __threadfence();
            atomicExch(&g_bar_gen, gen + 1);
        } else {
            while (*(volatile unsigned*)&g_bar_gen == gen) { __nanosleep(64); }
        }
        __threadfence();
    }
    __syncthreads();
}

// ---------------- one-time Wx0 transpose + bf16 hi/lo split ----------------
__global__ void prep_W(const float* __restrict__ W)
{
    __shared__ float t[32][33];
    const int k0 = blockIdx.x * 32;
    const int n0 = blockIdx.y * 32;

    for (int i = threadIdx.y; i < 32; i += 8)
        t[i][threadIdx.x] = W[(size_t)(k0 + i) * Gg + n0 + threadIdx.x];
    __syncthreads();

    for (int i = threadIdx.y; i < 32; i += 8) {
        float v = t[threadIdx.x][i];
        __nv_bfloat16 h = __float2bfloat16(v);
        __nv_bfloat16 l = __float2bfloat16(v - __bfloat162float(h));
        g_Wth[(size_t)(n0 + i) * KK + k0 + threadIdx.x] = h;
        g_Wtl[(size_t)(n0 + i) * KK + k0 + threadIdx.x] = l;
    }
}

// ---------------- one-time embedding bf16 hi/lo split ----------------
__global__ void prep_emb(const float* __restrict__ E)
{
    size_t i = ((size_t)blockIdx.x * 256 + threadIdx.x) * 4;
    float4 v = *(const float4*)(E + i);
    __nv_bfloat16 h0 = __float2bfloat16(v.x), h1 = __float2bfloat16(v.y);
    __nv_bfloat16 h2 = __float2bfloat16(v.z), h3 = __float2bfloat16(v.w);
    __nv_bfloat16 hi[4] = {h0, h1, h2, h3};
    __nv_bfloat16 lo[4] = {
        __float2bfloat16(v.x - __bfloat162float(h0)),
        __float2bfloat16(v.y - __bfloat162float(h1)),
        __float2bfloat16(v.z - __bfloat162float(h2)),
        __float2bfloat16(v.w - __bfloat162float(h3))};
    *(ull*)(g_Ah + i) = *(ull*)hi;
    *(ull*)(g_Al + i) = *(ull*)lo;
}

// ---------------- mma.sync big GEMM: g_EGX = emb(split) @ Wx0^T(split) ----------------
__global__ __launch_bounds__(GT_THREADS, 1) void gemm_tc()
{
    extern __shared__ char dsm[];
    const uint32_t smem0 = smem_u32(dsm);
    const uint32_t sbase = (smem0 + 1023u) & ~1023u;

    const int tid  = threadIdx.x;
    const int wid  = tid >> 5;
    const int lane = tid & 31;
    const int m0   = blockIdx.y * 128;
    const int n0   = blockIdx.x * 128;

    const __nv_bfloat16* Ah = g_Ah;
    const __nv_bfloat16* Al = g_Al;
    const __nv_bfloat16* Bh = g_Wth;
    const __nv_bfloat16* Bl = g_Wtl;

    const int mb = (wid & 3) * 32;
    const int nb = (wid >> 2) * 64;

    float acc[2][8][4];
#pragma unroll
    for (int mt = 0; mt < 2; mt++)
#pragma unroll
        for (int nt = 0; nt < 8; nt++)
#pragma unroll
            for (int q = 0; q < 4; q++) acc[mt][nt][q] = 0.f;

#define STAGE(c)                                                                   \
    {                                                                              \
        const int kb_ = (c) * GT_CHUNK;                                            \
        const uint32_t bb_ = sbase + ((c) & 1) * BUF_B;                            \
        _Pragma("unroll")                                                          \
        for (int it = 0; it < 16; ++it) {                                          \
            int lin = it * GT_THREADS + tid;                                       \
            int mat = lin >> 10;                                                   \
            int idx = lin & 1023;                                                  \
            int row = idx >> 3;                                                    \
            int u   = idx & 7;                                                     \
            const __nv_bfloat16* src;                                              \
            if (mat == 0)      src = Ah + (size_t)(m0 + row) * KK + kb_ + u * 8;   \
            else if (mat == 1) src = Al + (size_t)(m0 + row) * KK + kb_ + u * 8;   \
            else if (mat == 2) src = Bh + (size_t)(n0 + row) * KK + kb_ + u * 8;   \
            else               src = Bl + (size_t)(n0 + row) * KK + kb_ + u * 8;   \
            uint32_t off = (uint32_t)(row * 128 + u * 16);                         \
            uint32_t dst = bb_ + mat * TILE_B + SW128(off);                        \
            CP16(dst, src);                                                        \
        }                                                                          \
        CP_COMMIT();                                                               \
    }

    STAGE(0);

    const int arow = lane & 15;
    const int akoff = (lane >> 4) * 16;
    const int brow = (lane & 7) + ((lane >> 4) & 1) * 8;
    const int bkoff = ((lane >> 3) & 1) * 16;

    for (int c = 0; c < GT_NCH; ++c) {
        if (c + 1 < GT_NCH) { STAGE(c + 1); CP_WAIT1(); }
        else                { CP_WAIT0(); }
        __syncthreads();

        const uint32_t bb  = sbase + (c & 1) * BUF_B;
        const uint32_t sAh = bb;
        const uint32_t sAl = bb + TILE_B;
        const uint32_t sBh = bb + 2 * TILE_B;
        const uint32_t sBl = bb + 3 * TILE_B;

#pragma unroll
        for (int ks = 0; ks < 4; ++ks) {
            const int kb = ks * 32 + akoff;
            uint32_t ah0_, ah1_, ah2_, ah3_, ah4_, ah5_, ah6_, ah7_;
            uint32_t al0_, al1_, al2_, al3_, al4_, al5_, al6_, al7_;
            {
                uint32_t a0 = sAh + SW128((uint32_t)((mb + arow) * 128 + kb));
                uint32_t a1 = sAh + SW128((uint32_t)((mb + 16 + arow) * 128 + kb));
                LDSM4(ah0_, ah1_, ah2_, ah3_, a0);
                LDSM4(ah4_, ah5_, ah6_, ah7_, a1);
                uint32_t a2 = sAl + SW128((uint32_t)((mb + arow) * 128 + kb));
                uint32_t a3 = sAl + SW128((uint32_t)((mb + 16 + arow) * 128 + kb));
                LDSM4(al0_, al1_, al2_, al3_, a2);
                LDSM4(al4_, al5_, al6_, al7_, a3);
            }
            const int bkb = ks * 32 + bkoff;
#pragma unroll
            for (int np = 0; np < 4; ++np) {
                uint32_t r = (uint32_t)((nb + np * 16 + brow) * 128 + bkb);
                uint32_t bh0_, bh1_, bh2_, bh3_, bl0_, bl1_, bl2_, bl3_;
                LDSM4(bh0_, bh1_, bh2_, bh3_, sBh + SW128(r));
                LDSM4(bl0_, bl1_, bl2_, bl3_, sBl + SW128(r));

                MMA16816(acc[0][2 * np],     ah0_, ah1_, ah2_, ah3_, bh0_, bh1_);
                MMA16816(acc[0][2 * np],     ah0_, ah1_, ah2_, ah3_, bl0_, bl1_);
                MMA16816(acc[0][2 * np],     al0_, al1_, al2_, al3_, bh0_, bh1_);
                MMA16816(acc[1][2 * np],     ah4_, ah5_, ah6_, ah7_, bh0_, bh1_);
                MMA16816(acc[1][2 * np],     ah4_, ah5_, ah6_, ah7_, bl0_, bl1_);
                MMA16816(acc[1][2 * np],     al4_, al5_, al6_, al7_, bh0_, bh1_);
                MMA16816(acc[0][2 * np + 1], ah0_, ah1_, ah2_, ah3_, bh2_, bh3_);
                MMA16816(acc[0][2 * np + 1], ah0_, ah1_, ah2_, ah3_, bl2_, bl3_);
                MMA16816(acc[0][2 * np + 1], al0_, al1_, al2_, al3_, bh2_, bh3_);
                MMA16816(acc[1][2 * np + 1], ah4_, ah5_, ah6_, ah7_, bh2_, bh3_);
                MMA16816(acc[1][2 * np + 1], ah4_, ah5_, ah6_, ah7_, bl2_, bl3_);
                MMA16816(acc[1][2 * np + 1], al4_, al5_, al6_, al7_, bh2_, bh3_);
            }
        }
        __syncthreads();
    }
#undef STAGE

#pragma unroll
    for (int mt = 0; mt < 2; ++mt)
#pragma unroll
        for (int nt = 0; nt < 8; ++nt) {
            int m = m0 + mb + mt * 16 + (lane >> 2);
            int n = n0 + nb + nt * 8 + (lane & 3) * 2;
            float* p = g_EGX + (size_t)m * Gg + n;
            *(float2*)p = make_float2(acc[mt][nt][0], acc[mt][nt][1]);
            *(float2*)(p + 8 * Gg) = make_float2(acc[mt][nt][2], acc[mt][nt][3]);
        }
}

// ---------------- staging: 32-k chunk of h (hi/lo) into SW64 slot ----------------
__device__ __forceinline__ void stage32(uint32_t slot, int c,
                                        const __nv_bfloat16* hbh,
                                        const __nv_bfloat16* hbl, int tid)
{
    const int kb = c * CH2;
#pragma unroll
    for (int it = 0; it < 2; ++it) {
        int lin = it * NTHR + tid;          // 0..511
        int row = lin >> 2;
        int u   = lin & 3;
        uint32_t off = sw64((uint32_t)(row * 64 + u * 16));
        CP16(slot + off,        hbh + (size_t)row * KK + kb + u * 8);
        CP16(slot + 8192 + off, hbl + (size_t)row * KK + kb + u * 8);
    }
    CP_COMMIT();
}

// ---------------- fused layer-0: recurrence + GX1 on shared staged A ----------------
// SMEM: Wh0 hi/lo (96KB) + Wx1 hi/lo (96KB) + 2-slot A ring (32KB) = 224KB.
// Step t: stage h0[t-1]; MMA -> GH (Wh0, if t<512) and GX1[t-1] (Wx1, if t>=1).
__global__ __launch_bounds__(NTHR, 1) void gru0_fused(const int* __restrict__ X,
                                                      const float* __restrict__ Wh,
                                                      const float* __restrict__ Wx1,
                                                      const float* __restrict__ bias)
{
    extern __shared__ char dsm[];
    const uint32_t smem0 = smem_u32(dsm);
    const uint32_t base  = (smem0 + 1023u) & ~1023u;
    char* sm = dsm + (base - smem0);

    const uint32_t sWh = base;               // hi at +0, lo at +49152
    const uint32_t sWx = base + 98304u;
    const uint32_t sA  = base + 196608u;     // 2 slots x 16KB (hi 8KB, lo 8KB)

    const int tid  = threadIdx.x;
    const int wid  = tid >> 5;
    const int lane = tid & 31;
    const int j0   = blockIdx.x * 8;
    const int mbw  = wid * 16;

    // zero h buffer 0 slice
    {
        int idx = blockIdx.x * 256 + tid;
        ((ull*)g_hbh[0])[idx] = 0ull;
        ((ull*)g_hbl[0])[idx] = 0ull;
    }

    // one-time: 24 Wh0 cols + 24 Wx1 cols -> SMEM bf16 hi/lo, SW64 per 32-k chunk
    for (int idx = tid; idx < 48 * KK; idx += NTHR) {
        int n48 = idx % 48;
        int k   = idx / 48;
        int mat = (n48 >= 24) ? 1 : 0;
        int n   = n48 - mat * 24;
        int gate = n >> 3, jj = n & 7;
        const float* Wsrc = mat ? Wx1 : Wh;
        float v = Wsrc[(size_t)k * Gg + gate * Hh + j0 + jj];
        __nv_bfloat16 h = __float2bfloat16(v);
        __nv_bfloat16 l = __float2bfloat16(v - __bfloat162float(h));
        uint32_t off = (uint32_t)(k >> 5) * 1536u + sw64((uint32_t)(n * 64 + (k & 31) * 2));
        char* rb = sm + (size_t)mat * 98304u;
        *(__nv_bfloat16*)(rb + off)           = h;
        *(__nv_bfloat16*)(rb + 49152u + off)  = l;
    }

    const int bq0  = mbw + (lane >> 2);
    const int bq1  = bq0 + 8;
    const int jc   = (lane & 3) * 2;
    const int jcol = j0 + jc;

    const float2 bz0 = *(const float2*)&bias[jcol];
    const float2 br0 = *(const float2*)&bias[Hh + jcol];
    const float2 bn0 = *(const float2*)&bias[2 * Hh + jcol];
    const float2 bz1 = *(const float2*)&bias[Gg + jcol];
    const float2 br1 = *(const float2*)&bias[Gg + Hh + jcol];
    const float2 bn1 = *(const float2*)&bias[Gg + 2 * Hh + jcol];

    grid_barrier();   // zero-init + weight SMEM visible

    for (int t = 0; t <= Tt; ++t) {
        const int p = t & 1;
        const __nv_bfloat16* hbh = g_hbh[p];       // h[t-1]
        const __nv_bfloat16* hbl = g_hbl[p];
        __nv_bfloat16* hnh = g_hbh[p ^ 1];
        __nv_bfloat16* hnl = g_hbl[p ^ 1];
        const bool doRec = (t < Tt);

        float accG[3][4], accX[3][4];
#pragma unroll
        for (int g = 0; g < 3; g++)
#pragma unroll
            for (int q = 0; q < 4; q++) { accG[g][q] = 0.f; accX[g][q] = 0.f; }

        // prefetch embGX gather rows (consumed after MMA loop)
        float2 gxv[2][3];
        if (doRec) {
#pragma unroll
            for (int i = 0; i < 2; ++i) {
                int b = i ? bq1 : bq0;
                const float* gxrow = g_EGX + (size_t)__ldg(&X[b * Tt + t]) * Gg;
                gxv[i][0] = *(const float2*)&gxrow[jcol];
                gxv[i][1] = *(const float2*)&gxrow[Hh + jcol];
                gxv[i][2] = *(const float2*)&gxrow[2 * Hh + jcol];
            }
        }

        if (t >= 1) {
            stage32(sA, 0, hbh, hbl, tid);
            for (int c = 0; c < NCH2; ++c) {
                if (c + 1 < NCH2) {
                    stage32(sA + (uint32_t)((c + 1) & 1) * 16384u, c + 1, hbh, hbl, tid);
                    CP_WAIT1();
                } else {
                    CP_WAIT0();
                }
                __syncthreads();

                const uint32_t ab = sA + (uint32_t)(c & 1) * 16384u;
                const uint32_t wc = (uint32_t)c * 1536u;

#pragma unroll
                for (int ks = 0; ks < 2; ++ks) {
                    uint32_t aoff = sw64((uint32_t)((mbw + (lane & 15)) * 64 +
                                                    ks * 32 + (lane >> 4) * 16));
                    uint32_t ah0, ah1, ah2, ah3, al0, al1, al2, al3;
                    LDSM4(ah0, ah1, ah2, ah3, ab + aoff);
                    LDSM4(al0, al1, al2, al3, ab + 8192u + aoff);

                    uint32_t b4 = sw64((uint32_t)(((lane & 7) + ((lane >> 4) & 1) * 8) * 64 +
                                                  ks * 32 + ((lane >> 3) & 1) * 16));
                    uint32_t b2 = sw64((uint32_t)((16 + (lane & 7)) * 64 +
                                                  ks * 32 + ((lane >> 3) & 1) * 16));

                    if (doRec) {
                        uint32_t bh0, bh1, bh2, bh3, sh0, sh1;
                        uint32_t bl0, bl1, bl2, bl3, sl0, sl1;
                        LDSM4(bh0, bh1, bh2, bh3, sWh + wc + b4);
                        LDSM2(sh0, sh1,           sWh + wc + b2);
                        LDSM4(bl0, bl1, bl2, bl3, sWh + 49152u + wc + b4);
                        LDSM2(sl0, sl1,           sWh + 49152u + wc + b2);

                        MMA16816(accG[0], ah0, ah1, ah2, ah3, bh0, bh1);
                        MMA16816(accG[0], ah0, ah1, ah2, ah3, bl0, bl1);
                        MMA16816(accG[0], al0, al1, al2, al3, bh0, bh1);
                        MMA16816(accG[1], ah0, ah1, ah2, ah3, bh2, bh3);
                        MMA16816(accG[1], ah0, ah1, ah2, ah3, bl2, bl3);
                        MMA16816(accG[1], al0, al1, al2, al3, bh2, bh3);
                        MMA16816(accG[2], ah0, ah1, ah2, ah3, sh0, sh1);
                        MMA16816(accG[2], ah0, ah1, ah2, ah3, sl0, sl1);
                        MMA16816(accG[2], al0, al1, al2, al3, sh0, sh1);
                    }
                    {
                        uint32_t xh0, xh1, xh2, xh3, th0, th1;
                        uint32_t xl0, xl1, xl2, xl3, tl0, tl1;
                        LDSM4(xh0, xh1, xh2, xh3, sWx + wc + b4);
                        LDSM2(th0, th1,           sWx + wc + b2);
                        LDSM4(xl0, xl1, xl2, xl3, sWx + 49152u + wc + b4);
                        LDSM2(tl0, tl1,           sWx + 49152u + wc + b2);

                        MMA16816(accX[0], ah0, ah1, ah2, ah3, xh0, xh1);
                        MMA16816(accX[0], ah0, ah1, ah2, ah3, xl0, xl1);
                        MMA16816(accX[0], al0, al1, al2, al3, xh0, xh1);
                        MMA16816(accX[1], ah0, ah1, ah2, ah3, xh2, xh3);
                        MMA16816(accX[1], ah0, ah1, ah2, ah3, xl2, xl3);
                        MMA16816(accX[1], al0, al1, al2, al3, xh2, xh3);
                        MMA16816(accX[2], ah0, ah1, ah2, ah3, th0, th1);
                        MMA16816(accX[2], ah0, ah1, ah2, ah3, tl0, tl1);
                        MMA16816(accX[2], al0, al1, al2, al3, th0, th1);
                    }
                }
                __syncthreads();
            }

            // write GX1 rows for timestep t-1
            size_t rb0 = ((size_t)(t - 1) * Bsz + bq0) * Gg + jcol;
            size_t rb1 = ((size_t)(t - 1) * Bsz + bq1) * Gg + jcol;
#pragma unroll
            for (int g = 0; g < 3; ++g) {
                *(float2*)&g_GX1[rb0 + (size_t)g * Hh] = make_float2(accX[g][0], accX[g][1]);
                *(float2*)&g_GX1[rb1 + (size_t)g * Hh] = make_float2(accX[g][2], accX[g][3]);
            }
        }

        if (doRec) {
#pragma unroll
            for (int i = 0; i < 2; ++i) {
                int b = i ? bq1 : bq0;
                __nv_bfloat162 hh = *(const __nv_bfloat162*)&hbh[(size_t)b * Hh + jcol];
                __nv_bfloat162 hl = *(const __nv_bfloat162*)&hbl[(size_t)b * Hh + jcol];
                float hv2[2];
#pragma unroll
                for (int q = 0; q < 2; ++q) {
                    float xz = (q ? gxv[i][0].y : gxv[i][0].x) + (q ? bz0.y : bz0.x);
                    float xr = (q ? gxv[i][1].y : gxv[i][1].x) + (q ? br0.y : br0.x);
                    float xn = (q ? gxv[i][2].y : gxv[i][2].x) + (q ? bn0.y : bn0.x);
                    float hz = accG[0][i * 2 + q] + (q ? bz1.y : bz1.x);
                    float hr = accG[1][i * 2 + q] + (q ? br1.y : br1.x);
                    float hn = accG[2][i * 2 + q] + (q ? bn1.y : bn1.x);

                    float z = 1.f / (1.f + expf(-(xz + hz)));
                    float r = 1.f / (1.f + expf(-(xr + hr)));
                    float n = tanhf(xn + r * hn);

                    float hp = q ? (__bfloat162float(hh.y) + __bfloat162float(hl.y))
                                 : (__bfloat162float(hh.x) + __bfloat162float(hl.x));
                    hv2[q] = z * hp + (1.f - z) * n;
                }
                __nv_bfloat16 hi0 = __float2bfloat16(hv2[0]);
                __nv_bfloat16 hi1 = __float2bfloat16(hv2[1]);
                __nv_bfloat162 hiv; hiv.x = hi0; hiv.y = hi1;
                __nv_bfloat162 lov;
                lov.x = __float2bfloat16(hv2[0] - __bfloat162float(hi0));
                lov.y = __float2bfloat16(hv2[1] - __bfloat162float(hi1));

                *(__nv_bfloat162*)&hnh[(size_t)b * Hh + jcol] = hiv;
                *(__nv_bfloat162*)&hnl[(size_t)b * Hh + jcol] = lov;

                if (t == Tt - 1)
                    *(float2*)&g_hfin[0][(size_t)b * Hh + jcol] =
                        make_float2(hv2[0], hv2[1]);
            }
            grid_barrier();
        }
    }
}

// ---------------- layer-1 persistent MMA GRU (round-5 validated path) ----------------
__device__ __forceinline__ void stage_h(uint32_t sA, int c,
                                        const __nv_bfloat16* hbh,
                                        const __nv_bfloat16* hbl, int tid)
{
    const int kb = c * 64;
    const uint32_t ab = sA + (uint32_t)(c % 3) * 32768u;
#pragma unroll
    for (int it = 0; it < 4; ++it) {
        int lin = it * NTHR + tid;
        int row = lin >> 3;
        int u   = lin & 7;
        uint32_t off = SW128((uint32_t)(row * 128 + u * 16));
        CP16(ab + off,          hbh + (size_t)row * KK + kb + u * 8);
        CP16(ab + 16384 + off,  hbl + (size_t)row * KK + kb + u * 8);
    }
    CP_COMMIT();
}

__global__ __launch_bounds__(NTHR, 1) void gru1(const float* __restrict__ Wh,
                                                const float* __restrict__ bias,
                                                float* __restrict__ out)
{
    extern __shared__ char dsm[];
    const uint32_t smem0 = smem_u32(dsm);
    const uint32_t base  = (smem0 + 1023u) & ~1023u;
    char* sm = dsm + (base - smem0);

    const uint32_t sW = base;
    const uint32_t sWl = base + 49152u;
    const uint32_t sA = base + 98304u;

    const int tid  = threadIdx.x;
    const int wid  = tid >> 5;
    const int lane = tid & 31;
    const int j0   = blockIdx.x * 8;
    const int mbw  = wid * 16;

    {
        int idx = blockIdx.x * 256 + tid;
        ((ull*)g_hbh[0])[idx] = 0ull;
        ((ull*)g_hbl[0])[idx] = 0ull;
    }

    for (int pass = 0; pass < 128; ++pass) {
        int k = pass * 8 + (tid >> 5);
        int n = lane;
        if (n < 24) {
            int gate = n >> 3, jj = n & 7;
            float v = Wh[(size_t)k * Gg + gate * Hh + j0 + jj];
            __nv_bfloat16 h = __float2bfloat16(v);
            __nv_bfloat16 l = __float2bfloat16(v - __bfloat162float(h));
            int c = k >> 6, kp = k & 63;
            uint32_t off = (uint32_t)c * 3072u + SW128((uint32_t)(n * 128 + kp * 2));
            *(__nv_bfloat16*)(sm + off)           = h;
            *(__nv_bfloat16*)(sm + 49152u + off)  = l;
        }
    }

    const int bq0  = mbw + (lane >> 2);
    const int bq1  = bq0 + 8;
    const int jc   = (lane & 3) * 2;
    const int jcol = j0 + jc;

    const float2 bz0 = *(const float2*)&bias[jcol];
    const float2 br0 = *(const float2*)&bias[Hh + jcol];
    const float2 bn0 = *(const float2*)&bias[2 * Hh + jcol];
    const float2 bz1 = *(const float2*)&bias[Gg + jcol];
    const float2 br1 = *(const float2*)&bias[Gg + Hh + jcol];
    const float2 bn1 = *(const float2*)&bias[Gg + 2 * Hh + jcol];

    grid_barrier();

    for (int t = 0; t < Tt; ++t) {
        const int p = t & 1;
        const __nv_bfloat16* hbh = g_hbh[p];
        const __nv_bfloat16* hbl = g_hbl[p];
        __nv_bfloat16* hnh = g_hbh[p ^ 1];
        __nv_bfloat16* hnl = g_hbl[p ^ 1];

        float2 gxv[2][3];
#pragma unroll
        for (int i = 0; i < 2; ++i) {
            int b = i ? bq1 : bq0;
            const float* gxrow = g_GX1 + ((size_t)t * Bsz + b) * Gg;
            gxv[i][0] = *(const float2*)&gxrow[jcol];
            gxv[i][1] = *(const float2*)&gxrow[Hh + jcol];
            gxv[i][2] = *(const float2*)&gxrow[2 * Hh + jcol];
        }

        float acc[3][4];
#pragma unroll
        for (int g = 0; g < 3; g++)
#pragma unroll
            for (int q = 0; q < 4; q++) acc[g][q] = 0.f;

        if (t > 0) {
            stage_h(sA, 0, hbh, hbl, tid);
            stage_h(sA, 1, hbh, hbl, tid);

            for (int c = 0; c < 16; ++c) {
                if (c < 14) { CP_WAIT1(); }
                else        { CP_WAIT0(); }
                __syncthreads();
                if (c + 2 < 16) stage_h(sA, c + 2, hbh, hbl, tid);

                const uint32_t ab = sA + (uint32_t)(c % 3) * 32768u;
                const uint32_t wb  = sW  + (uint32_t)c * 3072u;
                const uint32_t wbl = sWl + (uint32_t)c * 3072u;

#pragma unroll
                for (int ks = 0; ks < 4; ++ks) {
                    uint32_t aoff = SW128((uint32_t)((mbw + (lane & 15)) * 128 +
                                                     ks * 32 + (lane >> 4) * 16));
                    uint32_t ah0, ah1, ah2, ah3, al0, al1, al2, al3;
                    LDSM4(ah0, ah1, ah2, ah3, ab + aoff);
                    LDSM4(al0, al1, al2, al3, ab + 16384u + aoff);

                    uint32_t boff4 = SW128((uint32_t)(((lane & 7) + ((lane >> 4) & 1) * 8) * 128 +
                                                      ks * 32 + ((lane >> 3) & 1) * 16));
                    uint32_t boff2 = SW128((uint32_t)((16 + (lane & 7)) * 128 +
                                                      ks * 32 + ((lane >> 3) & 1) * 16));
                    uint32_t bh0, bh1, bh2, bh3, bl0, bl1, bl2, bl3;
                    uint32_t sh0, sh1, sl0, sl1;
                    LDSM4(bh0, bh1, bh2, bh3, wb + boff4);
                    LDSM2(sh0, sh1, wb + boff2);
                    LDSM4(bl0, bl1, bl2, bl3, wbl + boff4);
                    LDSM2(sl0, sl1, wbl + boff2);

                    MMA16816(acc[0], ah0, ah1, ah2, ah3, bh0, bh1);
                    MMA16816(acc[0], ah0, ah1, ah2, ah3, bl0, bl1);
                    MMA16816(acc[0], al0, al1, al2, al3, bh0, bh1);
                    MMA16816(acc[1], ah0, ah1, ah2, ah3, bh2, bh3);
                    MMA16816(acc[1], ah0, ah1, ah2, ah3, bl2, bl3);
                    MMA16816(acc[1], al0, al1, al2, al3, bh2, bh3);
                    MMA16816(acc[2], ah0, ah1, ah2, ah3, sh0, sh1);
                    MMA16816(acc[2], ah0, ah1, ah2, ah3, sl0, sl1);
                    MMA16816(acc[2], al0, al1, al2, al3, sh0, sh1);
                }
            }
        }

#pragma unroll
        for (int i = 0; i < 2; ++i) {
            int b = i ? bq1 : bq0;
            __nv_bfloat162 hh = *(const __nv_bfloat162*)&hbh[(size_t)b * Hh + jcol];
            __nv_bfloat162 hl = *(const __nv_bfloat162*)&hbl[(size_t)b * Hh + jcol];
            float hv2[2];
#pragma unroll
            for (int q = 0; q < 2; ++q) {
                float xz = (q ? gxv[i][0].y : gxv[i][0].x) + (q ? bz0.y : bz0.x);
                float xr = (q ? gxv[i][1].y : gxv[i][1].x) + (q ? br0.y : br0.x);
                float xn = (q ? gxv[i][2].y : gxv[i][2].x) + (q ? bn0.y : bn0.x);
                float hz = acc[0][i * 2 + q] + (q ? bz1.y : bz1.x);
                float hr = acc[1][i * 2 + q] + (q ? br1.y : br1.x);
                float hn = acc[2][i * 2 + q] + (q ? bn1.y : bn1.x);

                float z = 1.f / (1.f + expf(-(xz + hz)));
                float r = 1.f / (1.f + expf(-(xr + hr)));
                float n = tanhf(xn + r * hn);

                float hp = q ? (__bfloat162float(hh.y) + __bfloat162float(hl.y))
                             : (__bfloat162float(hh.x) + __bfloat162float(hl.x));
                hv2[q] = z * hp + (1.f - z) * n;
            }
            __nv_bfloat16 hi0 = __float2bfloat16(hv2[0]);
            __nv_bfloat16 hi1 = __float2bfloat16(hv2[1]);
            __nv_bfloat162 hiv; hiv.x = hi0; hiv.y = hi1;
            __nv_bfloat162 lov;
            lov.x = __float2bfloat16(hv2[0] - __bfloat162float(hi0));
            lov.y = __float2bfloat16(hv2[1] - __bfloat162float(hi1));

            *(__nv_bfloat162*)&hnh[(size_t)b * Hh + jcol] = hiv;
            *(__nv_bfloat162*)&hnl[(size_t)b * Hh + jcol] = lov;

            *(float2*)&out[((size_t)b * Tt + t) * Hh + jcol] =
                make_float2(hv2[0], hv2[1]);

            if (t == Tt - 1)
                *(float2*)&g_hfin[1][(size_t)b * Hh + jcol] =
                    make_float2(hv2[0], hv2[1]);
        }

        grid_barrier();
    }
}

// ---------------- final-state copies ----------------
__global__ void copy_finals(float* __restrict__ out)
{
    int i = blockIdx.x * 256 + threadIdx.x;
    if (i < Bsz * Hh) {
        out[BTH + i] = g_hfin[0][i];
        out[BTH + (size_t)Bsz * Hh + i] = g_hfin[1][i];
    }
}

// ---------------- launch ----------------
extern "C" void kernel_launch(void* const* d_in, const int* in_sizes, int n_in,
                              void* d_out, int out_size)
{
    const int*   X   = (const int*)  d_in[0];
    const float* emb = (const float*)d_in[1];
    const float* Wx0 = (const float*)d_in[2];
    const float* Wh0 = (const float*)d_in[3];
    const float* b0  = (const float*)d_in[4];
    const float* Wx1 = (const float*)d_in[5];
    const float* Wh1 = (const float*)d_in[6];
    const float* b1  = (const float*)d_in[7];
    float* out = (float*)d_out;

    const int smem_g0 = 196608 + 2 * 16384 + 1024;   // 230400
    const int smem_g1 = 98304 + 3 * 32768 + 1024;
    const int smem_gt = 2 * BUF_B + 1024;
    cudaFuncSetAttribute(gru0_fused, cudaFuncAttributeMaxDynamicSharedMemorySize, smem_g0);
    cudaFuncSetAttribute(gru1,       cudaFuncAttributeMaxDynamicSharedMemorySize, smem_g1);
    cudaFuncSetAttribute(gemm_tc,    cudaFuncAttributeMaxDynamicSharedMemorySize, smem_gt);

    zero_bar<<<1, 1>>>();

    prep_W<<<dim3(KK / 32, Gg / 32), dim3(32, 8)>>>(Wx0);
    prep_emb<<<32000 * KK / 1024, 256>>>(emb);

    // embGX = emb @ Wx0
    gemm_tc<<<dim3(Gg / 128, 32000 / 128), GT_THREADS, smem_gt>>>();

    // layer 0 recurrence + fused GX1
    gru0_fused<<<NCTA, NTHR, smem_g0>>>(X, Wh0, Wx1, b0);

    // layer 1 recurrence
    gru1<<<NCTA, NTHR, smem_g1>>>(Wh1, b1, out);

    copy_finals<<<(Bsz * Hh + 255) / 256, 256>>>(out);
}

// round 7
// speedup vs baseline: 1.1776x; 1.1776x over previous
#include <cuda_runtime.h>
#include <cuda_bf16.h>
#include <math.h>
#include <stdint.h>

// Problem constants
#define Bsz 128
#define Tt  512
#define Hh  1024
#define Gg  3072
#define KK  1024
#define BTH ((size_t)Bsz * Tt * Hh)

// Recurrence config: 128 CTAs x 512 threads (16 warps, K-split warp pairs)
#define NCTA 128
#define NTHR 512

// Tensor GEMM config
#define GT_THREADS 256
#define GT_CHUNK   64
#define GT_NCH     (KK / GT_CHUNK)
#define TILE_B     (128 * 128)
#define BUF_B      (4 * TILE_B)

typedef unsigned long long ull;

// ---------------- device scratch ----------------
__device__ float g_GX[(size_t)Tt * Bsz * Gg];        // embGX [32000,3072] then GX1 [65536,3072]
__device__ __align__(16) __nv_bfloat16 g_Ah[(size_t)32000 * KK];
__device__ __align__(16) __nv_bfloat16 g_Al[(size_t)32000 * KK];
__device__ __align__(16) __nv_bfloat16 g_H0h[(size_t)Tt * Bsz * KK];
__device__ __align__(16) __nv_bfloat16 g_H0l[(size_t)Tt * Bsz * KK];
__device__ __align__(16) __nv_bfloat16 g_Wth[2][(size_t)Gg * KK];
__device__ __align__(16) __nv_bfloat16 g_Wtl[2][(size_t)Gg * KK];
__device__ __align__(16) __nv_bfloat16 g_hbh[2][Bsz * Hh];   // ping-pong h hi
__device__ __align__(16) __nv_bfloat16 g_hbl[2][Bsz * Hh];   // ping-pong h lo
__device__ float g_hfin[2][Bsz * Hh];
__device__ unsigned g_bar_count;
__device__ unsigned g_bar_gen;

// ---------------- helpers ----------------
__device__ __forceinline__ uint32_t smem_u32(const void* p)
{
    uint32_t a;
    asm("{ .reg .u64 t; cvta.to.shared.u64 t, %1; cvt.u32.u64 %0, t; }" : "=r"(a) : "l"(p));
    return a;
}

#define SW128(o) ((o) ^ (((o) >> 3) & 0x70))

#define CP16(dst, src) \
    asm volatile("cp.async.cg.shared.global [%0], [%1], 16;" :: "r"(dst), "l"(src) : "memory")

#define CP_COMMIT() asm volatile("cp.async.commit_group;" ::: "memory")
#define CP_WAIT1()  asm volatile("cp.async.wait_group 1;" ::: "memory")
#define CP_WAIT0()  asm volatile("cp.async.wait_group 0;" ::: "memory")

#define LDSM4(r0, r1, r2, r3, addr) \
    asm volatile("ldmatrix.sync.aligned.m8n8.x4.shared.b16 {%0,%1,%2,%3}, [%4];" \
                 : "=r"(r0), "=r"(r1), "=r"(r2), "=r"(r3) : "r"(addr))

#define LDSM2(r0, r1, addr) \
    asm volatile("ldmatrix.sync.aligned.m8n8.x2.shared.b16 {%0,%1}, [%2];" \
                 : "=r"(r0), "=r"(r1) : "r"(addr))

#define MMA16816(c, a0, a1, a2, a3, b0, b1) \
    asm volatile("mma.sync.aligned.m16n8k16.row.col.f32.bf16.bf16.f32 " \
                 "{%0,%1,%2,%3}, {%4,%5,%6,%7}, {%8,%9}, {%0,%1,%2,%3};" \
                 : "+f"((c)[0]), "+f"((c)[1]), "+f"((c)[2]), "+f"((c)[3]) \
                 : "r"(a0), "r"(a1), "r"(a2), "r"(a3), "r"(b0), "r"(b1))

// ---------------- init ----------------
__global__ void zero_bar()
{
    g_bar_count = 0;
    g_bar_gen   = 0;
}

// ---------------- grid barrier ----------------
__device__ __forceinline__ void grid_barrier()
{
    __threadfence();
    __syncthreads();
    if (threadIdx.x == 0) {
        unsigned gen = *(volatile unsigned*)&g_bar_gen;
        if (atomicAdd(&g_bar_count, 1) == NCTA - 1) {
            g_bar_count = 0;
            __threadfence();
            atomicExch(&g_bar_gen, gen + 1);
        } else {
            while (*(volatile unsigned*)&g_bar_gen == gen) { __nanosleep(64); }
        }
        __threadfence();
    }
    __syncthreads();
}

// ---------------- one-time weight transpose + bf16 hi/lo split ----------------
__global__ void prep_W(const float* __restrict__ W, int sel)
{
    __shared__ float t[32][33];
    const int k0 = blockIdx.x * 32;
    const int n0 = blockIdx.y * 32;

    for (int i = threadIdx.y; i < 32; i += 8)
        t[i][threadIdx.x] = W[(size_t)(k0 + i) * Gg + n0 + threadIdx.x];
    __syncthreads();

    __nv_bfloat16* Th = g_Wth[sel];
    __nv_bfloat16* Tl = g_Wtl[sel];
    for (int i = threadIdx.y; i < 32; i += 8) {
        float v = t[threadIdx.x][i];
        __nv_bfloat16 h = __float2bfloat16(v);
        __nv_bfloat16 l = __float2bfloat16(v - __bfloat162float(h));
        Th[(size_t)(n0 + i) * KK + k0 + threadIdx.x] = h;
        Tl[(size_t)(n0 + i) * KK + k0 + threadIdx.x] = l;
    }
}

// ---------------- one-time embedding bf16 hi/lo split ----------------
__global__ void prep_emb(const float* __restrict__ E)
{
    size_t i = ((size_t)blockIdx.x * 256 + threadIdx.x) * 4;
    float4 v = *(const float4*)(E + i);
    __nv_bfloat16 h0 = __float2bfloat16(v.x), h1 = __float2bfloat16(v.y);
    __nv_bfloat16 h2 = __float2bfloat16(v.z), h3 = __float2bfloat16(v.w);
    __nv_bfloat16 hi[4] = {h0, h1, h2, h3};
    __nv_bfloat16 lo[4] = {
        __float2bfloat16(v.x - __bfloat162float(h0)),
        __float2bfloat16(v.y - __bfloat162float(h1)),
        __float2bfloat16(v.z - __bfloat162float(h2)),
        __float2bfloat16(v.w - __bfloat162float(h3))};
    *(ull*)(g_Ah + i) = *(ull*)hi;
    *(ull*)(g_Al + i) = *(ull*)lo;
}

// ---------------- mma.sync big GEMM (validated) ----------------
__global__ __launch_bounds__(GT_THREADS, 1) void gemm_tc(int useH0, int wsel)
{
    extern __shared__ char dsm[];
    const uint32_t smem0 = smem_u32(dsm);
    const uint32_t sbase = (smem0 + 1023u) & ~1023u;

    const int tid  = threadIdx.x;
    const int wid  = tid >> 5;
    const int lane = tid & 31;
    const int m0   = blockIdx.y * 128;
    const int n0   = blockIdx.x * 128;

    const __nv_bfloat16* Ah = useH0 ? g_H0h : g_Ah;
    const __nv_bfloat16* Al = useH0 ? g_H0l : g_Al;
    const __nv_bfloat16* Bh = g_Wth[wsel];
    const __nv_bfloat16* Bl = g_Wtl[wsel];

    const int mb = (wid & 3) * 32;
    const int nb = (wid >> 2) * 64;

    float acc[2][8][4];
#pragma unroll
    for (int mt = 0; mt < 2; mt++)
#pragma unroll
        for (int nt = 0; nt < 8; nt++)
#pragma unroll
            for (int q = 0; q < 4; q++) acc[mt][nt][q] = 0.f;

#define STAGE(c)                                                                   \
    {                                                                              \
        const int kb_ = (c) * GT_CHUNK;                                            \
        const uint32_t bb_ = sbase + ((c) & 1) * BUF_B;                            \
        _Pragma("unroll")                                                          \
        for (int it = 0; it < 16; ++it) {                                          \
            int lin = it * GT_THREADS + tid;                                       \
            int mat = lin >> 10;                                                   \
            int idx = lin & 1023;                                                  \
            int row = idx >> 3;                                                    \
            int u   = idx & 7;                                                     \
            const __nv_bfloat16* src;                                              \
            if (mat == 0)      src = Ah + (size_t)(m0 + row) * KK + kb_ + u * 8;   \
            else if (mat == 1) src = Al + (size_t)(m0 + row) * KK + kb_ + u * 8;   \
            else if (mat == 2) src = Bh + (size_t)(n0 + row) * KK + kb_ + u * 8;   \
            else               src = Bl + (size_t)(n0 + row) * KK + kb_ + u * 8;   \
            uint32_t off = (uint32_t)(row * 128 + u * 16);                         \
            uint32_t dst = bb_ + mat * TILE_B + SW128(off);                        \
            CP16(dst, src);                                                        \
        }                                                                          \
        CP_COMMIT();                                                               \
    }

    STAGE(0);

    const int arow = lane & 15;
    const int akoff = (lane >> 4) * 16;
    const int brow = (lane & 7) + ((lane >> 4) & 1) * 8;
    const int bkoff = ((lane >> 3) & 1) * 16;

    for (int c = 0; c < GT_NCH; ++c) {
        if (c + 1 < GT_NCH) { STAGE(c + 1); CP_WAIT1(); }
        else                { CP_WAIT0(); }
        __syncthreads();

        const uint32_t bb  = sbase + (c & 1) * BUF_B;
        const uint32_t sAh = bb;
        const uint32_t sAl = bb + TILE_B;
        const uint32_t sBh = bb + 2 * TILE_B;
        const uint32_t sBl = bb + 3 * TILE_B;

#pragma unroll
        for (int ks = 0; ks < 4; ++ks) {
            const int kb = ks * 32 + akoff;
            uint32_t ah0_, ah1_, ah2_, ah3_, ah4_, ah5_, ah6_, ah7_;
            uint32_t al0_, al1_, al2_, al3_, al4_, al5_, al6_, al7_;
            {
                uint32_t a0 = sAh + SW128((uint32_t)((mb + arow) * 128 + kb));
                uint32_t a1 = sAh + SW128((uint32_t)((mb + 16 + arow) * 128 + kb));
                LDSM4(ah0_, ah1_, ah2_, ah3_, a0);
                LDSM4(ah4_, ah5_, ah6_, ah7_, a1);
                uint32_t a2 = sAl + SW128((uint32_t)((mb + arow) * 128 + kb));
                uint32_t a3 = sAl + SW128((uint32_t)((mb + 16 + arow) * 128 + kb));
                LDSM4(al0_, al1_, al2_, al3_, a2);
                LDSM4(al4_, al5_, al6_, al7_, a3);
            }
            const int bkb = ks * 32 + bkoff;
#pragma unroll
            for (int np = 0; np < 4; ++np) {
                uint32_t r = (uint32_t)((nb + np * 16 + brow) * 128 + bkb);
                uint32_t bh0_, bh1_, bh2_, bh3_, bl0_, bl1_, bl2_, bl3_;
                LDSM4(bh0_, bh1_, bh2_, bh3_, sBh + SW128(r));
                LDSM4(bl0_, bl1_, bl2_, bl3_, sBl + SW128(r));

                MMA16816(acc[0][2 * np],     ah0_, ah1_, ah2_, ah3_, bh0_, bh1_);
                MMA16816(acc[0][2 * np],     ah0_, ah1_, ah2_, ah3_, bl0_, bl1_);
                MMA16816(acc[0][2 * np],     al0_, al1_, al2_, al3_, bh0_, bh1_);
                MMA16816(acc[1][2 * np],     ah4_, ah5_, ah6_, ah7_, bh0_, bh1_);
                MMA16816(acc[1][2 * np],     ah4_, ah5_, ah6_, ah7_, bl0_, bl1_);
                MMA16816(acc[1][2 * np],     al4_, al5_, al6_, al7_, bh0_, bh1_);
                MMA16816(acc[0][2 * np + 1], ah0_, ah1_, ah2_, ah3_, bh2_, bh3_);
                MMA16816(acc[0][2 * np + 1], ah0_, ah1_, ah2_, ah3_, bl2_, bl3_);
                MMA16816(acc[0][2 * np + 1], al0_, al1_, al2_, al3_, bh2_, bh3_);
                MMA16816(acc[1][2 * np + 1], ah4_, ah5_, ah6_, ah7_, bh2_, bh3_);
                MMA16816(acc[1][2 * np + 1], ah4_, ah5_, ah6_, ah7_, bl2_, bl3_);
                MMA16816(acc[1][2 * np + 1], al4_, al5_, al6_, al7_, bh2_, bh3_);
            }
        }
        __syncthreads();
    }
#undef STAGE

#pragma unroll
    for (int mt = 0; mt < 2; ++mt)
#pragma unroll
        for (int nt = 0; nt < 8; ++nt) {
            int m = m0 + mb + mt * 16 + (lane >> 2);
            int n = n0 + nb + nt * 8 + (lane & 3) * 2;
            float* p = g_GX + (size_t)m * Gg + n;
            *(float2*)p = make_float2(acc[mt][nt][0], acc[mt][nt][1]);
            *(float2*)(p + 8 * Gg) = make_float2(acc[mt][nt][2], acc[mt][nt][3]);
        }
}

// ---------------- MMA staging for recurrence (512 threads) ----------------
__device__ __forceinline__ void stage_h(uint32_t sA, int c,
                                        const __nv_bfloat16* hbh,
                                        const __nv_bfloat16* hbl, int tid)
{
    const int kb = c * 64;
    const uint32_t ab = sA + (uint32_t)(c % 3) * 32768u;
#pragma unroll
    for (int it = 0; it < 2; ++it) {
        int lin = it * NTHR + tid;          // 0..1023
        int row = lin >> 3;
        int u   = lin & 7;
        uint32_t off = SW128((uint32_t)(row * 128 + u * 8 * 2));
        CP16(ab + off,          hbh + (size_t)row * KK + kb + u * 8);
        CP16(ab + 16384 + off,  hbl + (size_t)row * KK + kb + u * 8);
    }
    CP_COMMIT();
}

// ---------------- persistent MMA GRU layer (16 warps, K-split pairs) ----------------
// CTA owns h-cols [j0, j0+8). Warps w and w+8 share m-tile w:
// group A (w<8) does ks {0,1}, group B ks {2,3} of each 64-k chunk.
// Split-term accumulators (accH: Ah*Bh, accL: cross terms) for chain parallelism.
// End of step: group B writes partials to SMEM, group A reduces + runs gates.
__global__ __launch_bounds__(NTHR, 1) void gru_layer(const int* __restrict__ X,
                                                     const float* __restrict__ Wh,
                                                     const float* __restrict__ bias,
                                                     float* __restrict__ out,
                                                     int layer)
{
    extern __shared__ char dsm[];
    const uint32_t smem0 = smem_u32(dsm);
    const uint32_t base  = (smem0 + 1023u) & ~1023u;
    char* sm = dsm + (base - smem0);

    const uint32_t sW  = base;
    const uint32_t sWl = base + 49152u;
    const uint32_t sA  = base + 98304u;     // ring 3 x 32KB; reused for reduction

    const int tid   = threadIdx.x;
    const int wid   = tid >> 5;
    const int lane  = tid & 31;
    const int group = wid >> 3;             // 0 = A, 1 = B
    const int wm    = wid & 7;              // m-tile index
    const int j0    = blockIdx.x * 8;
    const int mbw   = wm * 16;
    const int ks0   = group * 2;

    // zero h buffer 0 slice
    if (tid < 256) {
        int idx = blockIdx.x * 256 + tid;
        ((ull*)g_hbh[0])[idx] = 0ull;
        ((ull*)g_hbl[0])[idx] = 0ull;
    }

    // one-time: 24 weight cols -> SMEM bf16 hi/lo, ldmatrix-swizzled per 64-k chunk
    for (int idx = tid; idx < 24 * KK; idx += NTHR) {
        int n = idx % 24;
        int k = idx / 24;
        int gate = n >> 3, jj = n & 7;
        float v = Wh[(size_t)k * Gg + gate * Hh + j0 + jj];
        __nv_bfloat16 h = __float2bfloat16(v);
        __nv_bfloat16 l = __float2bfloat16(v - __bfloat162float(h));
        int c = k >> 6, kp = k & 63;
        uint32_t off = (uint32_t)c * 3072u + SW128((uint32_t)(n * 128 + kp * 2));
        *(__nv_bfloat16*)(sm + off)           = h;
        *(__nv_bfloat16*)(sm + 49152u + off)  = l;
    }

    const int bq0  = mbw + (lane >> 2);
    const int bq1  = bq0 + 8;
    const int jc   = (lane & 3) * 2;
    const int jcol = j0 + jc;

    const float2 bz0 = *(const float2*)&bias[jcol];
    const float2 br0 = *(const float2*)&bias[Hh + jcol];
    const float2 bn0 = *(const float2*)&bias[2 * Hh + jcol];
    const float2 bz1 = *(const float2*)&bias[Gg + jcol];
    const float2 br1 = *(const float2*)&bias[Gg + Hh + jcol];
    const float2 bn1 = *(const float2*)&bias[Gg + 2 * Hh + jcol];

    grid_barrier();   // zero-init + weight SMEM visible

    for (int t = 0; t < Tt; ++t) {
        const int p = t & 1;
        const __nv_bfloat16* hbh = g_hbh[p];
        const __nv_bfloat16* hbl = g_hbl[p];
        __nv_bfloat16* hnh = g_hbh[p ^ 1];
        __nv_bfloat16* hnl = g_hbl[p ^ 1];

        // prefetch gx rows (group A only — it runs the gates)
        float2 gxv[2][3];
        if (group == 0) {
#pragma unroll
            for (int i = 0; i < 2; ++i) {
                int b = i ? bq1 : bq0;
                const float* gxrow;
                if (layer == 0)
                    gxrow = g_GX + (size_t)__ldg(&X[b * Tt + t]) * Gg;
                else
                    gxrow = g_GX + ((size_t)t * Bsz + b) * Gg;
                gxv[i][0] = *(const float2*)&gxrow[jcol];
                gxv[i][1] = *(const float2*)&gxrow[Hh + jcol];
                gxv[i][2] = *(const float2*)&gxrow[2 * Hh + jcol];
            }
        }

        float accH[3][4], accL[3][4];
#pragma unroll
        for (int g = 0; g < 3; g++)
#pragma unroll
            for (int q = 0; q < 4; q++) { accH[g][q] = 0.f; accL[g][q] = 0.f; }

        if (t > 0) {
            stage_h(sA, 0, hbh, hbl, tid);
            stage_h(sA, 1, hbh, hbl, tid);

            for (int c = 0; c < 16; ++c) {
                if (c < 14) { CP_WAIT1(); }
                else        { CP_WAIT0(); }
                __syncthreads();
                if (c + 2 < 16) stage_h(sA, c + 2, hbh, hbl, tid);

                const uint32_t ab  = sA + (uint32_t)(c % 3) * 32768u;
                const uint32_t wb  = sW  + (uint32_t)c * 3072u;
                const uint32_t wbl = sWl + (uint32_t)c * 3072u;

#pragma unroll
                for (int kq = 0; kq < 2; ++kq) {
                    const int ks = ks0 + kq;
                    uint32_t aoff = SW128((uint32_t)((mbw + (lane & 15)) * 128 +
                                                     ks * 32 + (lane >> 4) * 16));
                    uint32_t ah0, ah1, ah2, ah3, al0, al1, al2, al3;
                    LDSM4(ah0, ah1, ah2, ah3, ab + aoff);
                    LDSM4(al0, al1, al2, al3, ab + 16384u + aoff);

                    uint32_t boff4 = SW128((uint32_t)(((lane & 7) + ((lane >> 4) & 1) * 8) * 128 +
                                                      ks * 32 + ((lane >> 3) & 1) * 16));
                    uint32_t boff2 = SW128((uint32_t)((16 + (lane & 7)) * 128 +
                                                      ks * 32 + ((lane >> 3) & 1) * 16));
                    uint32_t bh0, bh1, bh2, bh3, bl0, bl1, bl2, bl3;
                    uint32_t sh0, sh1, sl0, sl1;
                    LDSM4(bh0, bh1, bh2, bh3, wb + boff4);
                    LDSM2(sh0, sh1, wb + boff2);
                    LDSM4(bl0, bl1, bl2, bl3, wbl + boff4);
                    LDSM2(sl0, sl1, wbl + boff2);

                    MMA16816(accH[0], ah0, ah1, ah2, ah3, bh0, bh1);
                    MMA16816(accL[0], ah0, ah1, ah2, ah3, bl0, bl1);
                    MMA16816(accL[0], al0, al1, al2, al3, bh0, bh1);
                    MMA16816(accH[1], ah0, ah1, ah2, ah3, bh2, bh3);
                    MMA16816(accL[1], ah0, ah1, ah2, ah3, bl2, bl3);
                    MMA16816(accL[1], al0, al1, al2, al3, bh2, bh3);
                    MMA16816(accH[2], ah0, ah1, ah2, ah3, sh0, sh1);
                    MMA16816(accL[2], ah0, ah1, ah2, ah3, sl0, sl1);
                    MMA16816(accL[2], al0, al1, al2, al3, sh0, sh1);
                }
            }
        }

        // combine split terms
        float tot[3][4];
#pragma unroll
        for (int g = 0; g < 3; g++)
#pragma unroll
            for (int q = 0; q < 4; q++) tot[g][q] = accH[g][q] + accL[g][q];

        if (t > 0) {
            // cross-group K reduction through ring SMEM (all cp.async consumed)
            __syncthreads();
            float* red = (float*)(sm + 98304u);
            const int slot = ((wm * 32) + lane) * 12;
            if (group == 1) {
#pragma unroll
                for (int g = 0; g < 3; g++)
#pragma unroll
                    for (int q = 0; q < 4; q++) red[slot + g * 4 + q] = tot[g][q];
            }
            __syncthreads();
            if (group == 0) {
#pragma unroll
                for (int g = 0; g < 3; g++)
#pragma unroll
                    for (int q = 0; q < 4; q++) tot[g][q] += red[slot + g * 4 + q];
            }
        }

        if (group == 0) {
#pragma unroll
            for (int i = 0; i < 2; ++i) {
                int b = i ? bq1 : bq0;
                __nv_bfloat162 hh = *(const __nv_bfloat162*)&hbh[(size_t)b * Hh + jcol];
                __nv_bfloat162 hl = *(const __nv_bfloat162*)&hbl[(size_t)b * Hh + jcol];
                float hv2[2];
#pragma unroll
                for (int q = 0; q < 2; ++q) {
                    float xz = (q ? gxv[i][0].y : gxv[i][0].x) + (q ? bz0.y : bz0.x);
                    float xr = (q ? gxv[i][1].y : gxv[i][1].x) + (q ? br0.y : br0.x);
                    float xn = (q ? gxv[i][2].y : gxv[i][2].x) + (q ? bn0.y : bn0.x);
                    float hz = tot[0][i * 2 + q] + (q ? bz1.y : bz1.x);
                    float hr = tot[1][i * 2 + q] + (q ? br1.y : br1.x);
                    float hn = tot[2][i * 2 + q] + (q ? bn1.y : bn1.x);

                    float z = 1.f / (1.f + expf(-(xz + hz)));
                    float r = 1.f / (1.f + expf(-(xr + hr)));
                    float n = tanhf(xn + r * hn);

                    float hp = q ? (__bfloat162float(hh.y) + __bfloat162float(hl.y))
                                 : (__bfloat162float(hh.x) + __bfloat162float(hl.x));
                    hv2[q] = z * hp + (1.f - z) * n;
                }
                __nv_bfloat16 hi0 = __float2bfloat16(hv2[0]);
                __nv_bfloat16 hi1 = __float2bfloat16(hv2[1]);
                __nv_bfloat162 hiv; hiv.x = hi0; hiv.y = hi1;
                __nv_bfloat162 lov;
                lov.x = __float2bfloat16(hv2[0] - __bfloat162float(hi0));
                lov.y = __float2bfloat16(hv2[1] - __bfloat162float(hi1));

                *(__nv_bfloat162*)&hnh[(size_t)b * Hh + jcol] = hiv;
                *(__nv_bfloat162*)&hnl[(size_t)b * Hh + jcol] = lov;

                if (layer == 0) {
                    size_t sidx = ((size_t)t * Bsz + b) * Hh + jcol;
                    *(__nv_bfloat162*)&g_H0h[sidx] = hiv;
                    *(__nv_bfloat162*)&g_H0l[sidx] = lov;
                } else {
                    *(float2*)&out[((size_t)b * Tt + t) * Hh + jcol] =
                        make_float2(hv2[0], hv2[1]);
                }
                if (t == Tt - 1)
                    *(float2*)&g_hfin[layer][(size_t)b * Hh + jcol] =
                        make_float2(hv2[0], hv2[1]);
            }
        }

        grid_barrier();
    }
}

// ---------------- final-state copies ----------------
__global__ void copy_finals(float* __restrict__ out)
{
    int i = blockIdx.x * 256 + threadIdx.x;
    if (i < Bsz * Hh) {
        out[BTH + i] = g_hfin[0][i];
        out[BTH + (size_t)Bsz * Hh + i] = g_hfin[1][i];
    }
}

// ---------------- launch ----------------
extern "C" void kernel_launch(void* const* d_in, const int* in_sizes, int n_in,
                              void* d_out, int out_size)
{
    const int*   X   = (const int*)  d_in[0];
    const float* emb = (const float*)d_in[1];
    const float* Wx0 = (const float*)d_in[2];
    const float* Wh0 = (const float*)d_in[3];
    const float* b0  = (const float*)d_in[4];
    const float* Wx1 = (const float*)d_in[5];
    const float* Wh1 = (const float*)d_in[6];
    const float* b1  = (const float*)d_in[7];
    float* out = (float*)d_out;

    const int smem_gru = 98304 + 3 * 32768 + 1024;
    const int smem_gt  = 2 * BUF_B + 1024;
    cudaFuncSetAttribute(gru_layer, cudaFuncAttributeMaxDynamicSharedMemorySize, smem_gru);
    cudaFuncSetAttribute(gemm_tc,  cudaFuncAttributeMaxDynamicSharedMemorySize, smem_gt);

    zero_bar<<<1, 1>>>();

    prep_W<<<dim3(KK / 32, Gg / 32), dim3(32, 8)>>>(Wx0, 0);
    prep_W<<<dim3(KK / 32, Gg / 32), dim3(32, 8)>>>(Wx1, 1);
    prep_emb<<<32000 * KK / 1024, 256>>>(emb);

    // embGX = emb @ Wx0
    gemm_tc<<<dim3(Gg / 128, 32000 / 128), GT_THREADS, smem_gt>>>(0, 0);

    // layer 0 recurrence (persistent, MMA, K-split warps)
    gru_layer<<<NCTA, NTHR, smem_gru>>>(X, Wh0, b0, out, 0);

    // GX1 = H0seq @ Wx1
    gemm_tc<<<dim3(Gg / 128, (Bsz * Tt) / 128), GT_THREADS, smem_gt>>>(1, 1);

    // layer 1 recurrence (persistent, MMA, K-split warps)
    gru_layer<<<NCTA, NTHR, smem_gru>>>(X, Wh1, b1, out, 1);

    copy_finals<<<(Bsz * Hh + 255) / 256, 256>>>(out);
}